// round 6
// baseline (speedup 1.0000x reference)
#include <cuda_runtime.h>
#include <cuda_fp16.h>
#include <cstdint>
#include <math.h>

#define NN 50000
#define EE 600000
#define FF 128
#define HH 128
#define CC 16
#define GG 500
#define NB 196   // ceil(NN/256)

// ---------------- scratch (device globals; zero-initialized at load) ---------
__device__ int    g_indeg[NN];
__device__ int    g_cursor[NN];
__device__ int    g_off[NN + 1];
__device__ float  g_dis[NN];
__device__ int    g_bsum[NB];
__device__ int2   g_csr[EE];                    // {src, weight bits}
__device__ __half g_h1h[(size_t)NN * HH];       // x @ W1 (fp16)
__device__ float  g_h2[(size_t)NN * CC];
__device__ float  g_pool[GG * CC];
__device__ float  g_cnt[GG];

// ---------------- degree count + zero pool/cnt --------------------------------
__global__ void k_deg(const int* __restrict__ dst) {
    int e = blockIdx.x * blockDim.x + threadIdx.x;
    if (e < GG * CC) g_pool[e] = 0.0f;
    if (e < GG) g_cnt[e] = 0.0f;
    if (e < EE) atomicAdd(&g_indeg[dst[e]], 1);
}

// ---------------- scan phase 1: per-block scan + dis (round-4 proven) ---------
__global__ __launch_bounds__(256) void k_part() {
    const int t = threadIdx.x;
    const int i = blockIdx.x * 256 + t;
    int v = (i < NN) ? g_indeg[i] : 0;
    if (i < NN) g_dis[i] = rsqrtf((float)v + 1.0f);   // +1 = self loop

    const int lane = t & 31, w = t >> 5;
    int x = v;
#pragma unroll
    for (int d = 1; d < 32; d <<= 1) {
        int y = __shfl_up_sync(0xffffffffu, x, d);
        if (lane >= d) x += y;
    }
    __shared__ int wsum[8];
    if (lane == 31) wsum[w] = x;
    __syncthreads();
    if (t < 8) {
        int y = wsum[t];
#pragma unroll
        for (int d = 1; d < 8; d <<= 1) {
            int z = __shfl_up_sync(0xffu, y, d);
            if (t >= d) y += z;
        }
        wsum[t] = y;
    }
    __syncthreads();
    int incl = x + ((w > 0) ? wsum[w - 1] : 0);
    if (i < NN) g_off[i] = incl - v;
    if (t == 255) g_bsum[blockIdx.x] = incl;
}

// ---------------- scan phase 2+3 fused: per-block base reduce + add (proven) ---
__global__ __launch_bounds__(256) void k_fin() {
    const int t = threadIdx.x;
    const int bid = blockIdx.x;
    int s = (t < bid) ? g_bsum[t] : 0;            // bid <= 195 < 256
    const int lane = t & 31, w = t >> 5;
#pragma unroll
    for (int d = 16; d; d >>= 1) s += __shfl_xor_sync(0xffffffffu, s, d);
    __shared__ int ws[8];
    if (lane == 0) ws[w] = s;
    __syncthreads();
    __shared__ int base;
    if (t == 0) {
        int b = 0;
#pragma unroll
        for (int j = 0; j < 8; j++) b += ws[j];
        base = b;
    }
    __syncthreads();
    int i = bid * 256 + t;
    if (i < NN) g_off[i] += base;
    if (bid == 0 && t == 0) g_off[NN] = EE;
}

// ---------------- CSR fill ------------------------------------------------------
__global__ void k_csr(const int* __restrict__ src, const int* __restrict__ dst) {
    int e = blockIdx.x * blockDim.x + threadIdx.x;
    if (e < EE) {
        int d = dst[e];
        int sN = src[e];
        int p = g_off[d] + atomicAdd(&g_cursor[d], 1);
        g_csr[p] = make_int2(sN, __float_as_int(g_dis[sN] * g_dis[d]));
    }
}

// ---------------- GEMM1: h1 = fp16( x @ W1 ), tensor cores ----------------------
#define LDH 72
__global__ __launch_bounds__(256) void k_gemm1(const float* __restrict__ x,
                                               const float* __restrict__ W1) {
    __shared__ __half As[128][LDH];
    __shared__ __half Bs[128][LDH];
    const int tid  = threadIdx.x;
    const int wid  = tid >> 5;
    const int lane = tid & 31;
    const int g    = lane >> 2;
    const int q    = lane & 3;
    const int m0   = blockIdx.x * 128;
    const int mw   = wid * 16;

    float acc[16][4];
#pragma unroll
    for (int n = 0; n < 16; n++)
#pragma unroll
        for (int c = 0; c < 4; c++) acc[n][c] = 0.0f;

    for (int k0 = 0; k0 < 128; k0 += 64) {
#pragma unroll
        for (int it = 0; it < 8; it++) {
            int idx = it * 256 + tid;
            int r   = idx >> 4;
            int c4  = idx & 15;
            float4 v = make_float4(0.f, 0.f, 0.f, 0.f);
            int row = m0 + r;
            if (row < NN) v = *(const float4*)(x + (size_t)row * 128 + k0 + c4 * 4);
            __half* p = &As[r][c4 * 4];
            *(__half2*)(p)     = __floats2half2_rn(v.x, v.y);
            *(__half2*)(p + 2) = __floats2half2_rn(v.z, v.w);
        }
#pragma unroll
        for (int it = 0; it < 32; it++) {
            int idx = it * 256 + tid;
            int kk  = idx >> 7;
            int n   = idx & 127;
            Bs[n][kk] = __float2half_rn(W1[(size_t)(k0 + kk) * 128 + n]);
        }
        __syncthreads();

#pragma unroll
        for (int ks = 0; ks < 4; ks++) {
            int kc = ks * 16 + q * 2;
            unsigned int a0 = *(const unsigned int*)&As[mw + g][kc];
            unsigned int a1 = *(const unsigned int*)&As[mw + g + 8][kc];
            unsigned int a2 = *(const unsigned int*)&As[mw + g][kc + 8];
            unsigned int a3 = *(const unsigned int*)&As[mw + g + 8][kc + 8];
#pragma unroll
            for (int nt = 0; nt < 16; nt++) {
                unsigned int b0 = *(const unsigned int*)&Bs[nt * 8 + g][kc];
                unsigned int b1 = *(const unsigned int*)&Bs[nt * 8 + g][kc + 8];
                asm volatile(
                    "mma.sync.aligned.m16n8k16.row.col.f32.f16.f16.f32 "
                    "{%0,%1,%2,%3}, {%4,%5,%6,%7}, {%8,%9}, {%0,%1,%2,%3};"
                    : "+f"(acc[nt][0]), "+f"(acc[nt][1]),
                      "+f"(acc[nt][2]), "+f"(acc[nt][3])
                    : "r"(a0), "r"(a1), "r"(a2), "r"(a3), "r"(b0), "r"(b1));
            }
        }
        __syncthreads();
    }

    const int r0 = m0 + mw + g;
#pragma unroll
    for (int nt = 0; nt < 16; nt++) {
        int n = nt * 8 + q * 2;
        if (r0 < NN)
            *(__half2*)&g_h1h[(size_t)r0 * 128 + n] = __floats2half2_rn(acc[nt][0], acc[nt][1]);
        if (r0 + 8 < NN)
            *(__half2*)&g_h1h[(size_t)(r0 + 8) * 128 + n] = __floats2half2_rn(acc[nt][2], acc[nt][3]);
    }
}

// ---------------- agg1 fused with GEMM2: h2 = relu(agg(h1)+b1) @ W2 -------------
__device__ __forceinline__ float4 h4_to_f4(uint2 v) {
    float2 lo = __half22float2(*(__half2*)&v.x);
    float2 hi = __half22float2(*(__half2*)&v.y);
    return make_float4(lo.x, lo.y, hi.x, hi.y);
}

__global__ __launch_bounds__(256) void k_agg1(const float* __restrict__ b1,
                                              const float* __restrict__ W2) {
    __shared__ float Ws[128][17];
    __shared__ float bsm[128];
    const int tid  = threadIdx.x;
    const int wid  = tid >> 5;
    const int lane = tid & 31;

#pragma unroll
    for (int it = 0; it < 8; it++) {
        int idx = it * 256 + tid;
        Ws[idx >> 4][idx & 15] = W2[idx];
    }
    if (tid < 128) bsm[tid] = b1[tid];

    // reset scratch for the NEXT run (consumers of these already finished)
    int gt = blockIdx.x * 256 + tid;
    if (gt < NN) { g_indeg[gt] = 0; g_cursor[gt] = 0; }
    __syncthreads();

    float wr[4][16];
#pragma unroll
    for (int f = 0; f < 4; f++)
#pragma unroll
        for (int c = 0; c < 16; c++) wr[f][c] = Ws[4 * lane + f][c];
    const float4 bb = make_float4(bsm[4 * lane], bsm[4 * lane + 1],
                                  bsm[4 * lane + 2], bsm[4 * lane + 3]);

    const uint2* __restrict__ h1 = (const uint2*)g_h1h;

#pragma unroll 1
    for (int it = 0; it < 8; it++) {
        const int node = blockIdx.x * 64 + wid * 8 + it;
        if (node >= NN) break;

        const float di = g_dis[node];
        const float w0 = di * di;
        float4 a = h4_to_f4(h1[(size_t)node * 32 + lane]);
        float4 acc = make_float4(a.x * w0, a.y * w0, a.z * w0, a.w * w0);

        int j = g_off[node];
        const int e = g_off[node + 1];
        for (; j + 1 < e; j += 2) {
            int2 c0 = g_csr[j];
            int2 c1 = g_csr[j + 1];
            float4 hA = h4_to_f4(h1[(size_t)c0.x * 32 + lane]);
            float4 hB = h4_to_f4(h1[(size_t)c1.x * 32 + lane]);
            float wA = __int_as_float(c0.y);
            float wB = __int_as_float(c1.y);
            acc.x = fmaf(hA.x, wA, acc.x); acc.y = fmaf(hA.y, wA, acc.y);
            acc.z = fmaf(hA.z, wA, acc.z); acc.w = fmaf(hA.w, wA, acc.w);
            acc.x = fmaf(hB.x, wB, acc.x); acc.y = fmaf(hB.y, wB, acc.y);
            acc.z = fmaf(hB.z, wB, acc.z); acc.w = fmaf(hB.w, wB, acc.w);
        }
        if (j < e) {
            int2 c0 = g_csr[j];
            float4 hA = h4_to_f4(h1[(size_t)c0.x * 32 + lane]);
            float wA = __int_as_float(c0.y);
            acc.x = fmaf(hA.x, wA, acc.x); acc.y = fmaf(hA.y, wA, acc.y);
            acc.z = fmaf(hA.z, wA, acc.z); acc.w = fmaf(hA.w, wA, acc.w);
        }
        // bias + relu -> this warp holds a1[node][0..127], 4 feats per lane
        acc.x = fmaxf(acc.x + bb.x, 0.0f);
        acc.y = fmaxf(acc.y + bb.y, 0.0f);
        acc.z = fmaxf(acc.z + bb.z, 0.0f);
        acc.w = fmaxf(acc.w + bb.w, 0.0f);

        // per-lane partials for all 16 classes
        float v[16];
#pragma unroll
        for (int c = 0; c < 16; c++)
            v[c] = fmaf(acc.x, wr[0][c],
                   fmaf(acc.y, wr[1][c],
                   fmaf(acc.z, wr[2][c], acc.w * wr[3][c])));

        // folding warp reduction: 16 values x 32 lanes -> class (lane>>1)&15
#pragma unroll
        for (int c = 0; c < 8; c++) {
            bool up = lane & 16;
            float aa = up ? v[c + 8] : v[c];
            float bv = up ? v[c] : v[c + 8];
            v[c] = aa + __shfl_xor_sync(0xffffffffu, bv, 16);
        }
#pragma unroll
        for (int c = 0; c < 4; c++) {
            bool up = lane & 8;
            float aa = up ? v[c + 4] : v[c];
            float bv = up ? v[c] : v[c + 4];
            v[c] = aa + __shfl_xor_sync(0xffffffffu, bv, 8);
        }
#pragma unroll
        for (int c = 0; c < 2; c++) {
            bool up = lane & 4;
            float aa = up ? v[c + 2] : v[c];
            float bv = up ? v[c] : v[c + 2];
            v[c] = aa + __shfl_xor_sync(0xffffffffu, bv, 4);
        }
        {
            bool up = lane & 2;
            float aa = up ? v[1] : v[0];
            float bv = up ? v[0] : v[1];
            v[0] = aa + __shfl_xor_sync(0xffffffffu, bv, 2);
        }
        v[0] += __shfl_xor_sync(0xffffffffu, v[0], 1);
        if (!(lane & 1)) g_h2[(size_t)node * 16 + (lane >> 1)] = v[0];
    }
}

// ---------------- aggregation layer 2 + mean pool --------------------------------
__global__ __launch_bounds__(128) void k_agg2_pool(const float* __restrict__ b2,
                                                   const int* __restrict__ batch) {
    const int tid  = threadIdx.x;
    const int lane = tid & 15;
    const int i    = blockIdx.x * 8 + (tid >> 4);
    if (i >= NN) return;
    const float di = g_dis[i];
    float acc = g_h2[(size_t)i * 16 + lane] * (di * di);
    const int s0 = g_off[i];
    const int s1 = g_off[i + 1];
    for (int j = s0; j < s1; j++) {
        int2 c0 = g_csr[j];
        acc = fmaf(g_h2[(size_t)c0.x * 16 + lane], __int_as_float(c0.y), acc);
    }
    acc += b2[lane];
    int b = batch[i];
    atomicAdd(&g_pool[b * 16 + lane], acc);
    if (lane == 0) atomicAdd(&g_cnt[b], 1.0f);
}

// ---------------- mean + log_softmax ---------------------------------------------
__global__ __launch_bounds__(256) void k_out(float* __restrict__ out) {
    const int tid = threadIdx.x;
    const int c = tid & 15;
    const int r = blockIdx.x * 16 + (tid >> 4);
    float v = 0.0f;
    if (r < GG) v = g_pool[r * 16 + c] / fmaxf(g_cnt[r], 1.0f);
    float m = v;
#pragma unroll
    for (int k = 8; k; k >>= 1) m = fmaxf(m, __shfl_xor_sync(0xffffffffu, m, k, 16));
    float e = expf(v - m);
    float s = e;
#pragma unroll
    for (int k = 8; k; k >>= 1) s += __shfl_xor_sync(0xffffffffu, s, k, 16);
    if (r < GG) out[r * 16 + c] = v - m - logf(s);
}

// -----------------------------------------------------------------------------------
extern "C" void kernel_launch(void* const* d_in, const int* in_sizes, int n_in,
                              void* d_out, int out_size) {
    const float* x   = (const float*)d_in[0];
    const float* W1  = (const float*)d_in[1];
    const float* b1  = (const float*)d_in[2];
    const float* W2  = (const float*)d_in[3];
    const float* b2  = (const float*)d_in[4];
    const int* esrc  = (const int*)d_in[5];
    const int* edst  = (const int*)d_in[6];
    const int* batch = (const int*)d_in[7];
    float* out = (float*)d_out;

    // fork: gemm1 (depends only on x,W1) overlaps graph prep on a side stream.
    cudaStream_t side;
    cudaEvent_t evA, evB;
    cudaStreamCreateWithFlags(&side, cudaStreamNonBlocking);
    cudaEventCreateWithFlags(&evA, cudaEventDisableTiming);
    cudaEventCreateWithFlags(&evB, cudaEventDisableTiming);

    cudaEventRecord(evA, 0);
    cudaStreamWaitEvent(side, evA, 0);
    k_gemm1<<<(NN + 127) / 128, 256, 0, side>>>(x, W1);
    cudaEventRecord(evB, side);

    k_deg<<<(EE + 255) / 256, 256>>>(edst);
    k_part<<<NB, 256>>>();
    k_fin<<<NB, 256>>>();
    k_csr<<<(EE + 255) / 256, 256>>>(esrc, edst);

    cudaStreamWaitEvent(0, evB, 0);
    k_agg1<<<(NN + 63) / 64, 256>>>(b1, W2);
    k_agg2_pool<<<(NN + 7) / 8, 128>>>(b2, batch);
    k_out<<<(GG + 15) / 16, 256>>>(out);
}

// round 8
// speedup vs baseline: 1.0973x; 1.0973x over previous
#include <cuda_runtime.h>
#include <cuda_fp16.h>
#include <cstdint>
#include <math.h>

#define NN 50000
#define EE 600000
#define FF 128
#define HH 128
#define CC 16
#define GG 500
#define NB 196   // ceil(NN/256)

// ---------------- scratch (device globals; zero-initialized at load) ---------
__device__ int    g_indeg[NN];
__device__ int    g_cursor[NN];
__device__ int    g_off[NN + 1];
__device__ float  g_dis[NN];
__device__ int    g_bsum[NB];
__device__ int2   g_csr[EE];                    // {src, weight bits}
__device__ __half g_h1h[(size_t)NN * HH];       // x @ W1 (fp16)
__device__ float  g_a1[(size_t)NN * HH];        // relu(agg(h1)+b1) fp32
__device__ float  g_h2[(size_t)NN * CC];
__device__ float  g_pool[GG * CC];
__device__ float  g_cnt[GG];

// ---------------- degree count + zero pool/cnt (proven round 6) ---------------
__global__ void k_deg(const int* __restrict__ dst) {
    int e = blockIdx.x * blockDim.x + threadIdx.x;
    if (e < GG * CC) g_pool[e] = 0.0f;
    if (e < GG) g_cnt[e] = 0.0f;
    if (e < EE) atomicAdd(&g_indeg[dst[e]], 1);
}

// ---------------- scan phase 1: per-block scan + dis (proven) -----------------
__global__ __launch_bounds__(256) void k_part() {
    const int t = threadIdx.x;
    const int i = blockIdx.x * 256 + t;
    int v = (i < NN) ? g_indeg[i] : 0;
    if (i < NN) g_dis[i] = rsqrtf((float)v + 1.0f);   // +1 = self loop

    const int lane = t & 31, w = t >> 5;
    int x = v;
#pragma unroll
    for (int d = 1; d < 32; d <<= 1) {
        int y = __shfl_up_sync(0xffffffffu, x, d);
        if (lane >= d) x += y;
    }
    __shared__ int wsum[8];
    if (lane == 31) wsum[w] = x;
    __syncthreads();
    if (t < 8) {
        int y = wsum[t];
#pragma unroll
        for (int d = 1; d < 8; d <<= 1) {
            int z = __shfl_up_sync(0xffu, y, d);
            if (t >= d) y += z;
        }
        wsum[t] = y;
    }
    __syncthreads();
    int incl = x + ((w > 0) ? wsum[w - 1] : 0);
    if (i < NN) g_off[i] = incl - v;
    if (t == 255) g_bsum[blockIdx.x] = incl;
}

// ---------------- scan phase 2+3: per-block base reduce + add (proven) --------
__global__ __launch_bounds__(256) void k_fin() {
    const int t = threadIdx.x;
    const int bid = blockIdx.x;
    int s = (t < bid) ? g_bsum[t] : 0;            // bid <= 195 < 256
    const int lane = t & 31, w = t >> 5;
#pragma unroll
    for (int d = 16; d; d >>= 1) s += __shfl_xor_sync(0xffffffffu, s, d);
    __shared__ int ws[8];
    if (lane == 0) ws[w] = s;
    __syncthreads();
    __shared__ int base;
    if (t == 0) {
        int b = 0;
#pragma unroll
        for (int j = 0; j < 8; j++) b += ws[j];
        base = b;
    }
    __syncthreads();
    int i = bid * 256 + t;
    if (i < NN) g_off[i] += base;
    if (bid == 0 && t == 0) g_off[NN] = EE;
}

// ---------------- CSR fill (proven) --------------------------------------------
__global__ void k_csr(const int* __restrict__ src, const int* __restrict__ dst) {
    int e = blockIdx.x * blockDim.x + threadIdx.x;
    if (e < EE) {
        int d = dst[e];
        int sN = src[e];
        int p = g_off[d] + atomicAdd(&g_cursor[d], 1);
        g_csr[p] = make_int2(sN, __float_as_int(g_dis[sN] * g_dis[d]));
    }
}

// ---------------- GEMM1: h1 = fp16( x @ W1 ), tensor cores (proven) ------------
#define LDH 72
__global__ __launch_bounds__(256) void k_gemm1(const float* __restrict__ x,
                                               const float* __restrict__ W1) {
    __shared__ __half As[128][LDH];
    __shared__ __half Bs[128][LDH];
    const int tid  = threadIdx.x;
    const int wid  = tid >> 5;
    const int lane = tid & 31;
    const int g    = lane >> 2;
    const int q    = lane & 3;
    const int m0   = blockIdx.x * 128;
    const int mw   = wid * 16;

    float acc[16][4];
#pragma unroll
    for (int n = 0; n < 16; n++)
#pragma unroll
        for (int c = 0; c < 4; c++) acc[n][c] = 0.0f;

    for (int k0 = 0; k0 < 128; k0 += 64) {
#pragma unroll
        for (int it = 0; it < 8; it++) {
            int idx = it * 256 + tid;
            int r   = idx >> 4;
            int c4  = idx & 15;
            float4 v = make_float4(0.f, 0.f, 0.f, 0.f);
            int row = m0 + r;
            if (row < NN) v = *(const float4*)(x + (size_t)row * 128 + k0 + c4 * 4);
            __half* p = &As[r][c4 * 4];
            *(__half2*)(p)     = __floats2half2_rn(v.x, v.y);
            *(__half2*)(p + 2) = __floats2half2_rn(v.z, v.w);
        }
#pragma unroll
        for (int it = 0; it < 32; it++) {
            int idx = it * 256 + tid;
            int kk  = idx >> 7;
            int n   = idx & 127;
            Bs[n][kk] = __float2half_rn(W1[(size_t)(k0 + kk) * 128 + n]);
        }
        __syncthreads();

#pragma unroll
        for (int ks = 0; ks < 4; ks++) {
            int kc = ks * 16 + q * 2;
            unsigned int a0 = *(const unsigned int*)&As[mw + g][kc];
            unsigned int a1 = *(const unsigned int*)&As[mw + g + 8][kc];
            unsigned int a2 = *(const unsigned int*)&As[mw + g][kc + 8];
            unsigned int a3 = *(const unsigned int*)&As[mw + g + 8][kc + 8];
#pragma unroll
            for (int nt = 0; nt < 16; nt++) {
                unsigned int b0 = *(const unsigned int*)&Bs[nt * 8 + g][kc];
                unsigned int b1 = *(const unsigned int*)&Bs[nt * 8 + g][kc + 8];
                asm volatile(
                    "mma.sync.aligned.m16n8k16.row.col.f32.f16.f16.f32 "
                    "{%0,%1,%2,%3}, {%4,%5,%6,%7}, {%8,%9}, {%0,%1,%2,%3};"
                    : "+f"(acc[nt][0]), "+f"(acc[nt][1]),
                      "+f"(acc[nt][2]), "+f"(acc[nt][3])
                    : "r"(a0), "r"(a1), "r"(a2), "r"(a3), "r"(b0), "r"(b1));
            }
        }
        __syncthreads();
    }

    const int r0 = m0 + mw + g;
#pragma unroll
    for (int nt = 0; nt < 16; nt++) {
        int n = nt * 8 + q * 2;
        if (r0 < NN)
            *(__half2*)&g_h1h[(size_t)r0 * 128 + n] = __floats2half2_rn(acc[nt][0], acc[nt][1]);
        if (r0 + 8 < NN)
            *(__half2*)&g_h1h[(size_t)(r0 + 8) * 128 + n] = __floats2half2_rn(acc[nt][2], acc[nt][3]);
    }
}

// ---------------- agg1: warp/node fp16 gathers, 4-way unroll, lean regs ---------
__device__ __forceinline__ float4 h4_to_f4(uint2 v) {
    float2 lo = __half22float2(*(__half2*)&v.x);
    float2 hi = __half22float2(*(__half2*)&v.y);
    return make_float4(lo.x, lo.y, hi.x, hi.y);
}

__global__ __launch_bounds__(256) void k_agg1(const float* __restrict__ b1) {
    const int gw   = (blockIdx.x * 256 + threadIdx.x) >> 5;   // node
    const int lane = threadIdx.x & 31;                         // 4-feat chunk
    // reset scratch for NEXT run (consumers already finished this run)
    {
        int gt = blockIdx.x * 256 + threadIdx.x;
        if (gt < NN) { g_indeg[gt] = 0; g_cursor[gt] = 0; }
    }
    if (gw >= NN) return;
    const uint2* __restrict__ h1 = (const uint2*)g_h1h;

    const float di = g_dis[gw];
    const float w0 = di * di;
    float4 a = h4_to_f4(h1[(size_t)gw * 32 + lane]);
    float4 acc = make_float4(a.x * w0, a.y * w0, a.z * w0, a.w * w0);

    int j = g_off[gw];
    const int e = g_off[gw + 1];
    for (; j + 3 < e; j += 4) {
        int2 c0 = g_csr[j];
        int2 c1 = g_csr[j + 1];
        int2 c2 = g_csr[j + 2];
        int2 c3 = g_csr[j + 3];
        uint2 r0 = h1[(size_t)c0.x * 32 + lane];
        uint2 r1 = h1[(size_t)c1.x * 32 + lane];
        uint2 r2 = h1[(size_t)c2.x * 32 + lane];
        uint2 r3 = h1[(size_t)c3.x * 32 + lane];
        float4 hA = h4_to_f4(r0), hB = h4_to_f4(r1);
        float4 hC = h4_to_f4(r2), hD = h4_to_f4(r3);
        float wA = __int_as_float(c0.y), wB = __int_as_float(c1.y);
        float wC = __int_as_float(c2.y), wD = __int_as_float(c3.y);
        acc.x = fmaf(hA.x, wA, acc.x); acc.y = fmaf(hA.y, wA, acc.y);
        acc.z = fmaf(hA.z, wA, acc.z); acc.w = fmaf(hA.w, wA, acc.w);
        acc.x = fmaf(hB.x, wB, acc.x); acc.y = fmaf(hB.y, wB, acc.y);
        acc.z = fmaf(hB.z, wB, acc.z); acc.w = fmaf(hB.w, wB, acc.w);
        acc.x = fmaf(hC.x, wC, acc.x); acc.y = fmaf(hC.y, wC, acc.y);
        acc.z = fmaf(hC.z, wC, acc.z); acc.w = fmaf(hC.w, wC, acc.w);
        acc.x = fmaf(hD.x, wD, acc.x); acc.y = fmaf(hD.y, wD, acc.y);
        acc.z = fmaf(hD.z, wD, acc.z); acc.w = fmaf(hD.w, wD, acc.w);
    }
    for (; j < e; j++) {
        int2 c0 = g_csr[j];
        float4 hA = h4_to_f4(h1[(size_t)c0.x * 32 + lane]);
        float wA = __int_as_float(c0.y);
        acc.x = fmaf(hA.x, wA, acc.x); acc.y = fmaf(hA.y, wA, acc.y);
        acc.z = fmaf(hA.z, wA, acc.z); acc.w = fmaf(hA.w, wA, acc.w);
    }
    float4 bb = ((const float4*)b1)[lane];
    float4 o = make_float4(fmaxf(acc.x + bb.x, 0.0f), fmaxf(acc.y + bb.y, 0.0f),
                           fmaxf(acc.z + bb.z, 0.0f), fmaxf(acc.w + bb.w, 0.0f));
    ((float4*)g_a1)[(size_t)gw * 32 + lane] = o;
}

// ---------------- GEMM2: h2 = a1 @ W2 (proven round 4) --------------------------
__global__ __launch_bounds__(256) void k_gemm2(const float* __restrict__ W2) {
    __shared__ float WsT[16][132];
    const int tid = threadIdx.x;
#pragma unroll
    for (int it = 0; it < 8; it++) {
        int idx = tid + it * 256;
        int k = idx >> 4, c = idx & 15;
        WsT[c][k] = W2[idx];
    }
    __syncthreads();

    int gid = blockIdx.x * 256 + tid;   // exact: 50000*16/256 = 3125 blocks
    int i = gid >> 4;
    int c = gid & 15;
    const float4* __restrict__ row = (const float4*)(g_a1 + (size_t)i * 128);
    const float* wt = WsT[c];
    float acc = 0.0f;
#pragma unroll
    for (int k4 = 0; k4 < 32; k4++) {
        float4 a = row[k4];
        float4 w = *(const float4*)(wt + k4 * 4);
        acc = fmaf(a.x, w.x, acc);
        acc = fmaf(a.y, w.y, acc);
        acc = fmaf(a.z, w.z, acc);
        acc = fmaf(a.w, w.w, acc);
    }
    g_h2[(size_t)i * 16 + c] = acc;
}

// ---------------- aggregation layer 2 + mean pool (proven) ----------------------
__global__ __launch_bounds__(128) void k_agg2_pool(const float* __restrict__ b2,
                                                   const int* __restrict__ batch) {
    const int tid  = threadIdx.x;
    const int lane = tid & 15;
    const int i    = blockIdx.x * 8 + (tid >> 4);
    if (i >= NN) return;
    const float di = g_dis[i];
    float acc = g_h2[(size_t)i * 16 + lane] * (di * di);
    const int s0 = g_off[i];
    const int s1 = g_off[i + 1];
    for (int j = s0; j < s1; j++) {
        int2 c0 = g_csr[j];
        acc = fmaf(g_h2[(size_t)c0.x * 16 + lane], __int_as_float(c0.y), acc);
    }
    acc += b2[lane];
    int b = batch[i];
    atomicAdd(&g_pool[b * 16 + lane], acc);
    if (lane == 0) atomicAdd(&g_cnt[b], 1.0f);
}

// ---------------- mean + log_softmax (proven) -----------------------------------
__global__ __launch_bounds__(256) void k_out(float* __restrict__ out) {
    const int tid = threadIdx.x;
    const int c = tid & 15;
    const int r = blockIdx.x * 16 + (tid >> 4);
    float v = 0.0f;
    if (r < GG) v = g_pool[r * 16 + c] / fmaxf(g_cnt[r], 1.0f);
    float m = v;
#pragma unroll
    for (int k = 8; k; k >>= 1) m = fmaxf(m, __shfl_xor_sync(0xffffffffu, m, k, 16));
    float e = expf(v - m);
    float s = e;
#pragma unroll
    for (int k = 8; k; k >>= 1) s += __shfl_xor_sync(0xffffffffu, s, k, 16);
    if (r < GG) out[r * 16 + c] = v - m - logf(s);
}

// -----------------------------------------------------------------------------------
extern "C" void kernel_launch(void* const* d_in, const int* in_sizes, int n_in,
                              void* d_out, int out_size) {
    const float* x   = (const float*)d_in[0];
    const float* W1  = (const float*)d_in[1];
    const float* b1  = (const float*)d_in[2];
    const float* W2  = (const float*)d_in[3];
    const float* b2  = (const float*)d_in[4];
    const int* esrc  = (const int*)d_in[5];
    const int* edst  = (const int*)d_in[6];
    const int* batch = (const int*)d_in[7];
    float* out = (float*)d_out;

    // one side stream + two events (this exact pattern passed rounds 4 and 6)
    cudaStream_t side;
    cudaEvent_t evA, evB;
    cudaStreamCreateWithFlags(&side, cudaStreamNonBlocking);
    cudaEventCreateWithFlags(&evA, cudaEventDisableTiming);
    cudaEventCreateWithFlags(&evB, cudaEventDisableTiming);

    cudaEventRecord(evA, 0);
    cudaStreamWaitEvent(side, evA, 0);
    k_gemm1<<<(NN + 127) / 128, 256, 0, side>>>(x, W1);
    cudaEventRecord(evB, side);

    k_deg<<<(EE + 255) / 256, 256>>>(edst);
    k_part<<<NB, 256>>>();
    k_fin<<<NB, 256>>>();
    k_csr<<<(EE + 255) / 256, 256>>>(esrc, edst);

    cudaStreamWaitEvent(0, evB, 0);
    k_agg1<<<(NN * 32 + 255) / 256, 256>>>(b1);
    k_gemm2<<<(NN * CC) / 256, 256>>>(W2);
    k_agg2_pool<<<(NN + 7) / 8, 128>>>(b2, batch);
    k_out<<<(GG + 15) / 16, 256>>>(out);
}

// round 9
// speedup vs baseline: 1.3232x; 1.2059x over previous
#include <cuda_runtime.h>
#include <cuda_fp16.h>
#include <cstdint>
#include <math.h>

#define NN 50000
#define EE 600000
#define FF 128
#define HH 128
#define CC 16
#define GG 500
#define NB 196   // ceil(NN/256)
#define LDH 72   // halves per smem row (64 used + 8 pad); 144B stride

// ---------------- scratch (device globals; zero-initialized at load) ---------
__device__ int    g_indeg[NN];
__device__ int    g_cursor[NN];
__device__ int    g_offl[NN];        // block-local exclusive offsets
__device__ int    g_off[NN + 1];     // final offsets (written by k_csr)
__device__ float  g_dis[NN];
__device__ int    g_bsum[NB];
__device__ int2   g_csr[EE];                    // {src, weight bits}
__device__ __half g_W1h[2][128][LDH];           // preconverted W1^T (B layout)
__device__ __half g_h1h[(size_t)NN * HH];       // x @ W1 (fp16)
__device__ __half g_a1h[(size_t)NN * HH];       // relu(agg(h1)+b1) fp16
__device__ float  g_h2[(size_t)NN * CC];
__device__ float  g_pool[GG * CC];
__device__ float  g_cnt[GG];

// ---------------- W1 -> fp16 B-layout, once (side stream) ---------------------
__global__ __launch_bounds__(256) void k_w1cvt(const float* __restrict__ W1) {
    int idx = blockIdx.x * 256 + threadIdx.x;     // 0..16383
    if (idx < 2 * 8192) {
        int h   = idx >> 13;          // k-half
        int rem = idx & 8191;
        int kk  = rem >> 7;           // 0..63
        int n   = rem & 127;
        g_W1h[h][n][kk] = __float2half_rn(W1[(size_t)(h * 64 + kk) * 128 + n]);
    }
}

// ---------------- degree count + zero pool/cnt --------------------------------
__global__ void k_deg(const int* __restrict__ dst) {
    int e = blockIdx.x * blockDim.x + threadIdx.x;
    if (e < GG * CC) g_pool[e] = 0.0f;
    if (e < GG) g_cnt[e] = 0.0f;
    if (e < EE) atomicAdd(&g_indeg[dst[e]], 1);
}

// ---------------- scan phase 1: per-block scan + dis ---------------------------
__global__ __launch_bounds__(256) void k_part() {
    const int t = threadIdx.x;
    const int i = blockIdx.x * 256 + t;
    int v = (i < NN) ? g_indeg[i] : 0;
    if (i < NN) g_dis[i] = rsqrtf((float)v + 1.0f);   // +1 = self loop

    const int lane = t & 31, w = t >> 5;
    int x = v;
#pragma unroll
    for (int d = 1; d < 32; d <<= 1) {
        int y = __shfl_up_sync(0xffffffffu, x, d);
        if (lane >= d) x += y;
    }
    __shared__ int wsum[8];
    if (lane == 31) wsum[w] = x;
    __syncthreads();
    if (t < 8) {
        int y = wsum[t];
#pragma unroll
        for (int d = 1; d < 8; d <<= 1) {
            int z = __shfl_up_sync(0xffu, y, d);
            if (t >= d) y += z;
        }
        wsum[t] = y;
    }
    __syncthreads();
    int incl = x + ((w > 0) ? wsum[w - 1] : 0);
    if (i < NN) g_offl[i] = incl - v;       // local exclusive
    if (t == 255) g_bsum[blockIdx.x] = incl;
}

// ---------------- CSR fill + offset finalization (k_fin folded in) -------------
__global__ __launch_bounds__(256) void k_csr(const int* __restrict__ src,
                                             const int* __restrict__ dst) {
    const int t   = threadIdx.x;
    const int bid = blockIdx.x;
    const int lane = t & 31, w = t >> 5;

    // smem scan of the 196 block sums -> exclusive base per part-block
    __shared__ int sbase[256];
    __shared__ int wsum[8];
    int v = (t < NB) ? g_bsum[t] : 0;
    int x = v;
#pragma unroll
    for (int d = 1; d < 32; d <<= 1) {
        int y = __shfl_up_sync(0xffffffffu, x, d);
        if (lane >= d) x += y;
    }
    if (lane == 31) wsum[w] = x;
    __syncthreads();
    if (t < 8) {
        int y = wsum[t];
#pragma unroll
        for (int d = 1; d < 8; d <<= 1) {
            int z = __shfl_up_sync(0xffu, y, d);
            if (t >= d) y += z;
        }
        wsum[t] = y;
    }
    __syncthreads();
    sbase[t] = (x + ((w > 0) ? wsum[w - 1] : 0)) - v;   // exclusive
    __syncthreads();

    const int e = bid * 256 + t;
    if (e < EE) {
        int d  = dst[e];
        int sN = src[e];
        int off_d = g_offl[d] + sbase[d >> 8];
        int p = off_d + atomicAdd(&g_cursor[d], 1);
        g_csr[p] = make_int2(sN, __float_as_int(g_dis[sN] * g_dis[d]));
    }
    // finalize g_off for downstream kernels (separate array -> no race)
    if (bid < NB) {
        int i = bid * 256 + t;
        if (i < NN) g_off[i] = g_offl[i] + sbase[bid];
    }
    if (bid == 0 && t == 0) g_off[NN] = EE;
}

// ---------------- GEMM1: h1 = fp16( x @ W1 ), tensor cores ---------------------
__global__ __launch_bounds__(256) void k_gemm1(const float* __restrict__ x) {
    __shared__ __half As[128][LDH];
    __shared__ __half Bs[128][LDH];
    const int tid  = threadIdx.x;
    const int wid  = tid >> 5;
    const int lane = tid & 31;
    const int g    = lane >> 2;
    const int q    = lane & 3;
    const int m0   = blockIdx.x * 128;
    const int mw   = wid * 16;

    float acc[16][4];
#pragma unroll
    for (int n = 0; n < 16; n++)
#pragma unroll
        for (int c = 0; c < 4; c++) acc[n][c] = 0.0f;

    for (int k0 = 0; k0 < 128; k0 += 64) {
        // load x tile half-K (fp32 -> fp16 convert)
#pragma unroll
        for (int it = 0; it < 8; it++) {
            int idx = it * 256 + tid;
            int r   = idx >> 4;
            int c4  = idx & 15;
            float4 v = make_float4(0.f, 0.f, 0.f, 0.f);
            int row = m0 + r;
            if (row < NN) v = *(const float4*)(x + (size_t)row * 128 + k0 + c4 * 4);
            __half* p = &As[r][c4 * 4];
            *(__half2*)(p)     = __floats2half2_rn(v.x, v.y);
            *(__half2*)(p + 2) = __floats2half2_rn(v.z, v.w);
        }
        // bulk-copy preconverted W1^T tile (1152 uint4)
        {
            const uint4* srcB = (const uint4*)&g_W1h[k0 >> 6][0][0];
            uint4* dstB = (uint4*)&Bs[0][0];
#pragma unroll
            for (int it = 0; it < 5; it++) {
                int idx = it * 256 + tid;
                if (idx < (128 * LDH * 2) / 16) dstB[idx] = srcB[idx];
            }
        }
        __syncthreads();

#pragma unroll
        for (int ks = 0; ks < 4; ks++) {
            int kc = ks * 16 + q * 2;
            unsigned int a0 = *(const unsigned int*)&As[mw + g][kc];
            unsigned int a1 = *(const unsigned int*)&As[mw + g + 8][kc];
            unsigned int a2 = *(const unsigned int*)&As[mw + g][kc + 8];
            unsigned int a3 = *(const unsigned int*)&As[mw + g + 8][kc + 8];
#pragma unroll
            for (int nt = 0; nt < 16; nt++) {
                unsigned int b0 = *(const unsigned int*)&Bs[nt * 8 + g][kc];
                unsigned int b1 = *(const unsigned int*)&Bs[nt * 8 + g][kc + 8];
                asm volatile(
                    "mma.sync.aligned.m16n8k16.row.col.f32.f16.f16.f32 "
                    "{%0,%1,%2,%3}, {%4,%5,%6,%7}, {%8,%9}, {%0,%1,%2,%3};"
                    : "+f"(acc[nt][0]), "+f"(acc[nt][1]),
                      "+f"(acc[nt][2]), "+f"(acc[nt][3])
                    : "r"(a0), "r"(a1), "r"(a2), "r"(a3), "r"(b0), "r"(b1));
            }
        }
        __syncthreads();
    }

    const int r0 = m0 + mw + g;
#pragma unroll
    for (int nt = 0; nt < 16; nt++) {
        int n = nt * 8 + q * 2;
        if (r0 < NN)
            *(__half2*)&g_h1h[(size_t)r0 * 128 + n] = __floats2half2_rn(acc[nt][0], acc[nt][1]);
        if (r0 + 8 < NN)
            *(__half2*)&g_h1h[(size_t)(r0 + 8) * 128 + n] = __floats2half2_rn(acc[nt][2], acc[nt][3]);
    }
}

// ---------------- agg1: warp/node fp16 gathers, 4-way unroll --------------------
__device__ __forceinline__ float4 h4_to_f4(uint2 v) {
    float2 lo = __half22float2(*(__half2*)&v.x);
    float2 hi = __half22float2(*(__half2*)&v.y);
    return make_float4(lo.x, lo.y, hi.x, hi.y);
}

__global__ __launch_bounds__(256) void k_agg1(const float* __restrict__ b1) {
    const int gw   = (blockIdx.x * 256 + threadIdx.x) >> 5;   // node
    const int lane = threadIdx.x & 31;                         // 4-feat chunk
    // reset scratch for NEXT run (consumers already finished this run)
    {
        int gt = blockIdx.x * 256 + threadIdx.x;
        if (gt < NN) { g_indeg[gt] = 0; g_cursor[gt] = 0; }
    }
    if (gw >= NN) return;
    const uint2* __restrict__ h1 = (const uint2*)g_h1h;

    const float di = g_dis[gw];
    const float w0 = di * di;
    float4 a = h4_to_f4(h1[(size_t)gw * 32 + lane]);
    float4 acc = make_float4(a.x * w0, a.y * w0, a.z * w0, a.w * w0);

    int j = g_off[gw];
    const int e = g_off[gw + 1];
    for (; j + 3 < e; j += 4) {
        int2 c0 = g_csr[j];
        int2 c1 = g_csr[j + 1];
        int2 c2 = g_csr[j + 2];
        int2 c3 = g_csr[j + 3];
        uint2 r0 = h1[(size_t)c0.x * 32 + lane];
        uint2 r1 = h1[(size_t)c1.x * 32 + lane];
        uint2 r2 = h1[(size_t)c2.x * 32 + lane];
        uint2 r3 = h1[(size_t)c3.x * 32 + lane];
        float4 hA = h4_to_f4(r0), hB = h4_to_f4(r1);
        float4 hC = h4_to_f4(r2), hD = h4_to_f4(r3);
        float wA = __int_as_float(c0.y), wB = __int_as_float(c1.y);
        float wC = __int_as_float(c2.y), wD = __int_as_float(c3.y);
        acc.x = fmaf(hA.x, wA, acc.x); acc.y = fmaf(hA.y, wA, acc.y);
        acc.z = fmaf(hA.z, wA, acc.z); acc.w = fmaf(hA.w, wA, acc.w);
        acc.x = fmaf(hB.x, wB, acc.x); acc.y = fmaf(hB.y, wB, acc.y);
        acc.z = fmaf(hB.z, wB, acc.z); acc.w = fmaf(hB.w, wB, acc.w);
        acc.x = fmaf(hC.x, wC, acc.x); acc.y = fmaf(hC.y, wC, acc.y);
        acc.z = fmaf(hC.z, wC, acc.z); acc.w = fmaf(hC.w, wC, acc.w);
        acc.x = fmaf(hD.x, wD, acc.x); acc.y = fmaf(hD.y, wD, acc.y);
        acc.z = fmaf(hD.z, wD, acc.z); acc.w = fmaf(hD.w, wD, acc.w);
    }
    for (; j < e; j++) {
        int2 c0 = g_csr[j];
        float4 hA = h4_to_f4(h1[(size_t)c0.x * 32 + lane]);
        float wA = __int_as_float(c0.y);
        acc.x = fmaf(hA.x, wA, acc.x); acc.y = fmaf(hA.y, wA, acc.y);
        acc.z = fmaf(hA.z, wA, acc.z); acc.w = fmaf(hA.w, wA, acc.w);
    }
    float4 bb = ((const float4*)b1)[lane];
    float ox = fmaxf(acc.x + bb.x, 0.0f);
    float oy = fmaxf(acc.y + bb.y, 0.0f);
    float oz = fmaxf(acc.z + bb.z, 0.0f);
    float ow = fmaxf(acc.w + bb.w, 0.0f);
    __half2 p0 = __floats2half2_rn(ox, oy);
    __half2 p1 = __floats2half2_rn(oz, ow);
    uint2 st;
    st.x = *(unsigned int*)&p0;
    st.y = *(unsigned int*)&p1;
    ((uint2*)g_a1h)[(size_t)gw * 32 + lane] = st;
}

// ---------------- GEMM2: h2 = a1(fp16) @ W2 -------------------------------------
__global__ __launch_bounds__(256) void k_gemm2(const float* __restrict__ W2) {
    __shared__ float WsT[16][132];   // transposed, padded
    const int tid = threadIdx.x;
#pragma unroll
    for (int it = 0; it < 8; it++) {
        int idx = tid + it * 256;
        int k = idx >> 4, c = idx & 15;
        WsT[c][k] = W2[idx];
    }
    __syncthreads();

    int gid = blockIdx.x * 256 + tid;   // exact: 50000*16/256 = 3125 blocks
    int i = gid >> 4;
    int c = gid & 15;
    const uint4* __restrict__ row = (const uint4*)(g_a1h + (size_t)i * 128);
    const float* wt = WsT[c];
    float acc = 0.0f;
#pragma unroll
    for (int k8 = 0; k8 < 16; k8++) {
        uint4 u = row[k8];
        float2 f0 = __half22float2(*(__half2*)&u.x);
        float2 f1 = __half22float2(*(__half2*)&u.y);
        float2 f2 = __half22float2(*(__half2*)&u.z);
        float2 f3 = __half22float2(*(__half2*)&u.w);
        const float* wk = wt + k8 * 8;
        acc = fmaf(f0.x, wk[0], acc); acc = fmaf(f0.y, wk[1], acc);
        acc = fmaf(f1.x, wk[2], acc); acc = fmaf(f1.y, wk[3], acc);
        acc = fmaf(f2.x, wk[4], acc); acc = fmaf(f2.y, wk[5], acc);
        acc = fmaf(f3.x, wk[6], acc); acc = fmaf(f3.y, wk[7], acc);
    }
    g_h2[(size_t)i * 16 + c] = acc;
}

// ---------------- aggregation layer 2 + mean pool (2-way unroll) ----------------
__global__ __launch_bounds__(128) void k_agg2_pool(const float* __restrict__ b2,
                                                   const int* __restrict__ batch) {
    const int tid  = threadIdx.x;
    const int lane = tid & 15;
    const int i    = blockIdx.x * 8 + (tid >> 4);
    if (i >= NN) return;
    const float di = g_dis[i];
    float acc = g_h2[(size_t)i * 16 + lane] * (di * di);
    int j = g_off[i];
    const int s1 = g_off[i + 1];
    for (; j + 1 < s1; j += 2) {
        int2 c0 = g_csr[j];
        int2 c1 = g_csr[j + 1];
        float hA = g_h2[(size_t)c0.x * 16 + lane];
        float hB = g_h2[(size_t)c1.x * 16 + lane];
        acc = fmaf(hA, __int_as_float(c0.y), acc);
        acc = fmaf(hB, __int_as_float(c1.y), acc);
    }
    if (j < s1) {
        int2 c0 = g_csr[j];
        acc = fmaf(g_h2[(size_t)c0.x * 16 + lane], __int_as_float(c0.y), acc);
    }
    acc += b2[lane];
    int b = batch[i];
    atomicAdd(&g_pool[b * 16 + lane], acc);
    if (lane == 0) atomicAdd(&g_cnt[b], 1.0f);
}

// ---------------- mean + log_softmax ---------------------------------------------
__global__ __launch_bounds__(256) void k_out(float* __restrict__ out) {
    const int tid = threadIdx.x;
    const int c = tid & 15;
    const int r = blockIdx.x * 16 + (tid >> 4);
    float v = 0.0f;
    if (r < GG) v = g_pool[r * 16 + c] / fmaxf(g_cnt[r], 1.0f);
    float m = v;
#pragma unroll
    for (int k = 8; k; k >>= 1) m = fmaxf(m, __shfl_xor_sync(0xffffffffu, m, k, 16));
    float e = expf(v - m);
    float s = e;
#pragma unroll
    for (int k = 8; k; k >>= 1) s += __shfl_xor_sync(0xffffffffu, s, k, 16);
    if (r < GG) out[r * 16 + c] = v - m - logf(s);
}

// -----------------------------------------------------------------------------------
extern "C" void kernel_launch(void* const* d_in, const int* in_sizes, int n_in,
                              void* d_out, int out_size) {
    const float* x   = (const float*)d_in[0];
    const float* W1  = (const float*)d_in[1];
    const float* b1  = (const float*)d_in[2];
    const float* W2  = (const float*)d_in[3];
    const float* b2  = (const float*)d_in[4];
    const int* esrc  = (const int*)d_in[5];
    const int* edst  = (const int*)d_in[6];
    const int* batch = (const int*)d_in[7];
    float* out = (float*)d_out;

    // one side stream + two events (exact resource pattern proven in rounds 4/6/8)
    cudaStream_t side;
    cudaEvent_t evA, evB;
    cudaStreamCreateWithFlags(&side, cudaStreamNonBlocking);
    cudaEventCreateWithFlags(&evA, cudaEventDisableTiming);
    cudaEventCreateWithFlags(&evB, cudaEventDisableTiming);

    cudaEventRecord(evA, 0);
    cudaStreamWaitEvent(side, evA, 0);
    k_w1cvt<<<64, 256, 0, side>>>(W1);
    k_gemm1<<<(NN + 127) / 128, 256, 0, side>>>(x);
    cudaEventRecord(evB, side);

    k_deg<<<(EE + 255) / 256, 256>>>(edst);
    k_part<<<NB, 256>>>();
    k_csr<<<(EE + 255) / 256, 256>>>(esrc, edst);

    cudaStreamWaitEvent(0, evB, 0);
    k_agg1<<<(NN * 32 + 255) / 256, 256>>>(b1);
    k_gemm2<<<(NN * CC) / 256, 256>>>(W2);
    k_agg2_pool<<<(NN + 7) / 8, 128>>>(b2, batch);
    k_out<<<(GG + 15) / 16, 256>>>(out);
}